// round 9
// baseline (speedup 1.0000x reference)
#include <cuda_runtime.h>

// HONU degree-3: out[r] = sum_{a<=b<=c} w(a,b,c) * xs[a][r]*xs[b][r]*xs[c][r]
// xs[0][r]=1 (bias). Weight index = lexicographic rank (closed form); the
// comb_idx input is redundant and ignored.
//
// Pair factorization: s_ab[r] = sum_c w_abc * xs[c][r];
//                     out[r] += xs[a][r]*xs[b][r]*s_ab[r].
// Two kernels:
//  1) honu_prep: rewrite w into g_wdup[pair][..]: each weight DUPLICATED
//     (w,w) so it is a ready f32x2 operand, rows zero-padded to float4
//     multiples (16B-aligned). Kills pack2 MOVs / prefetch copies / tail code
//     that dominated the issue stream in R7.
//  2) honu_main: 8 'a'-streams share each xs[c]; 4 rows/thread as 2x
//     fma.rn.f32x2. One LDG.128 per stream = 2 c-steps of weights. Work split
//     at 2-c-step "unit" granularity via smem prefix tables. Grid=148 (1
//     wave), 512 thr. Cross-block reduction fused via atomic ticket.

#define NFEAT 129
#define NROW  256
#define NBLK  148
#define WPB   16
#define NRANGE (NBLK * WPB / 2)   // 1184 ranges (2 warps each: row halves)

__host__ __device__ __forceinline__ int c2i(int v) { return v * (v - 1) / 2; }
__host__ __device__ __forceinline__ int c3i(int v) { return v * (v - 1) * (v - 2) / 6; }

// flat lexicographic rank of combo (a, b, b); total combos = C(131,3) = 366145
__device__ __forceinline__ int comb_base(int a, int b) {
    return 366145 - c3i(131 - a) + c2i(130 - a) - c2i(130 - b);
}

// units(b) = ceil(L/2), L = 129-b.  Row b: padded to 4*units floats in g_wdup.
// T2 = total blocked units over all (b, octet) rows.
__host__ __device__ constexpr int units_of(int b) { return (130 - b) >> 1; }
__host__ __device__ constexpr int t2_calc() {
    int t = 0;
    for (int b = 0; b < NFEAT; b++) t += (b / 8 + 1) * units_of(b);
    return t;
}
constexpr int T2 = t2_calc();

__host__ __device__ constexpr int wdup_total() {
    int t = 0;
    for (int b = 0; b < NFEAT; b++) t += (b + 1) * 4 * units_of(b);
    return t;
}
static_assert(wdup_total() <= 750000, "wdup size");

__device__ __align__(16) float g_wdup[wdup_total()];
__device__ float g_partial[NBLK * NROW];
__device__ int   g_count = 0;

__device__ __forceinline__ void fma2(unsigned long long& d, unsigned long long a,
                                     unsigned long long b) {
    asm("fma.rn.f32x2 %0, %1, %2, %0;" : "+l"(d) : "l"(a), "l"(b));
}
__device__ __forceinline__ unsigned long long mul2(unsigned long long a,
                                                   unsigned long long b) {
    unsigned long long d;
    asm("mul.rn.f32x2 %0, %1, %2;" : "=l"(d) : "l"(a), "l"(b));
    return d;
}
__device__ __forceinline__ ulonglong2 ldg128(const ulonglong2* p) {
    ulonglong2 v;
    asm("ld.global.nc.v2.u64 {%0,%1}, [%2];" : "=l"(v.x), "=l"(v.y) : "l"(p));
    return v;
}

// ---------------------------------------------------------------------------
// Prep: w -> g_wdup (duplicated + padded). Block a handles all pairs (a, b>=a).
// base2(a,b) = PH2[a] + H2[a] - H2[b],  H2[t] = sum_{b>=t} 4*units(b),
// PH2[a] = sum_{a'<a} H2[a'] = sum_b 4*units(b)*min(b+1, a).
// ---------------------------------------------------------------------------
__global__ void __launch_bounds__(256, 1)
honu_prep(const float* __restrict__ w) {
    __shared__ int sH2[131];
    int a = blockIdx.x;          // 0..128
    int tid = threadIdx.x;

    if (tid < 131) {
        int h = 0;
        for (int b = tid; b <= 128; b++) h += 4 * units_of(b);
        sH2[tid] = h;
    }
    __syncthreads();

    int PH2a = 0;
    for (int b = 0; b <= 128; b++) {
        int cnt = (b + 1 < a) ? (b + 1) : a;
        PH2a += 4 * units_of(b) * cnt;
    }

    int warp = tid >> 5, lane = tid & 31;
    for (int b = a + warp; b <= 128; b += 8) {
        int L = NFEAT - b;
        int dupN = units_of(b) * 2;            // duplicated slots (>= L)
        const float* src = w + comb_base(a, b);
        float2* dst = (float2*)(g_wdup + (PH2a + sH2[a] - sH2[b]));
        for (int k = lane; k < dupN; k += 32) {
            float v = (k < L) ? __ldg(src + k) : 0.0f;
            dst[k] = make_float2(v, v);
        }
    }
}

// ---------------------------------------------------------------------------
// Main kernel
// ---------------------------------------------------------------------------
__global__ void __launch_bounds__(512, 1)
honu_main(const float* __restrict__ x, float* __restrict__ out) {
    extern __shared__ float smem[];
    float* xs   = smem;                   // [130][256] feature-major (129 zeroed)
    float* obuf = smem + 130 * NROW;      // [16][128] per-warp half-row partials
    __shared__ int sH2[131], sPH2[131], sP2[131];
    __shared__ int is_last;

    int tid = threadIdx.x;

    // ---- tables ----
    if (tid < 131) {
        int h = 0;
        for (int b = tid; b <= 128; b++) h += 4 * units_of(b);
        sH2[tid] = h;
        int p = 0;
        for (int b = 0; b < tid && b <= 128; b++) p += (b / 8 + 1) * units_of(b);
        sP2[tid] = p;                      // sP2[129] == T2
        int q = 0;
        for (int b = 0; b <= 128; b++) {
            int cnt = (b + 1 < tid) ? (b + 1) : tid;
            q += 4 * units_of(b) * cnt;
        }
        sPH2[tid] = q;
    }

    // ---- x transposed into smem (both 256-thread halves do 64 features) ----
    {
        int r = tid & 255, h = tid >> 8;
        const float4* xg = (const float4*)(x + (size_t)r * 128 + h * 64);
#pragma unroll
        for (int k = 0; k < 16; k++) {
            float4 v = xg[k];
            int f = h * 64 + 4 * k;
            xs[(f + 1) * NROW + r] = v.x;
            xs[(f + 2) * NROW + r] = v.y;
            xs[(f + 3) * NROW + r] = v.z;
            xs[(f + 4) * NROW + r] = v.w;
        }
        if (h == 0) xs[r] = 1.0f;          // bias feature
        else        xs[129 * NROW + r] = 0.0f;  // pad feature
    }
    __syncthreads();

    int warp = tid >> 5, lane = tid & 31;
    int worker = blockIdx.x * WPB + warp;
    int range = worker >> 1;
    int rh    = worker & 1;                // 0 -> rows 0-127, 1 -> rows 128-255

    int s = (int)(((long long)T2 * range) / NRANGE);
    int e = (int)(((long long)T2 * (range + 1)) / NRANGE);

    // decode start -> (b, octet o, unit u0)
    int lo = 0, hi = 128;
    while (lo < hi) {
        int mid = (lo + hi + 1) >> 1;
        if (sP2[mid] <= s) lo = mid; else hi = mid - 1;
    }
    int b = lo;
    int rem = s - sP2[b];
    int nU = units_of(b);
    int o = rem / nU;
    int u0 = rem % nU;
    int pos = s;

    unsigned long long ov0 = 0, ov1 = 0;   // 4 rows as 2x f32x2

    const ulonglong2* xs2   = (const ulonglong2*)xs;       // 64 quads / feature
    const ulonglong2* wdup2 = (const ulonglong2*)g_wdup;   // float4 units
    const int lq = rh * 32 + lane;

    while (pos < e) {
        nU = units_of(b);
        int a0 = o << 3;
        int na = b + 1 - a0;
        if (na > 8) na = 8;
        int segU = nU - u0;
        if (segU > e - pos) segU = e - pos;

        int widx[8];                       // float4-unit index into g_wdup
        int h2b = sH2[b];
#pragma unroll
        for (int j = 0; j < 8; j++) {
            int aj = (j < na) ? (a0 + j) : a0;
            widx[j] = ((sPH2[aj] + sH2[aj] - h2b) >> 2) + u0;
        }

        unsigned long long acc[8][2];
#pragma unroll
        for (int j = 0; j < 8; j++) { acc[j][0] = 0; acc[j][1] = 0; }

        const ulonglong2* xq = xs2 + ((size_t)(b + 2 * u0) * 64 + lq);

        for (int i = 0; i < segU; i++) {
            ulonglong2 wv[8];
#pragma unroll
            for (int j = 0; j < 8; j++) wv[j] = ldg128(wdup2 + widx[j] + i);
            ulonglong2 x0 = xq[0];
            ulonglong2 x1 = xq[64];
            xq += 128;
#pragma unroll
            for (int j = 0; j < 8; j++) {
                fma2(acc[j][0], wv[j].x, x0.x);
                fma2(acc[j][1], wv[j].x, x0.y);
                fma2(acc[j][0], wv[j].y, x1.x);
                fma2(acc[j][1], wv[j].y, x1.y);
            }
        }

        // epilogue: out += (x_a * x_b) * s_ab  (linearity allows partial runs)
        {
            ulonglong2 xb = xs2[(size_t)b * 64 + lq];
#pragma unroll
            for (int j = 0; j < 8; j++) {
                if (j < na) {
                    ulonglong2 xa = xs2[(size_t)(a0 + j) * 64 + lq];
                    fma2(ov0, mul2(xa.x, xb.x), acc[j][0]);
                    fma2(ov1, mul2(xa.y, xb.y), acc[j][1]);
                }
            }
        }

        pos += segU;
        u0 += segU;
        if (u0 == nU) {
            u0 = 0;
            o++;
            if ((o << 3) > b) { o = 0; b++; }
        }
    }

    // ---- per-warp half-row partials -> smem, block combine -> global ----
    {
        float4* ob = (float4*)(obuf + warp * 128);
        union { unsigned long long q[2]; float4 f; } u;
        u.q[0] = ov0; u.q[1] = ov1;
        ob[lane] = u.f;                    // rows rh*128 + 4*lane .. +3
    }
    __syncthreads();
    if (tid < NROW) {
        int trh = tid >> 7, rr = tid & 127;
        float ssum = 0.0f;
#pragma unroll
        for (int k = 0; k < 8; k++) ssum += obuf[(2 * k + trh) * 128 + rr];
        g_partial[blockIdx.x * NROW + tid] = ssum;
    }

    // ---- fused cross-block reduction: last block reduces ----
    __threadfence();
    __syncthreads();
    if (tid == 0) is_last = (atomicAdd(&g_count, 1) == NBLK - 1);
    __syncthreads();
    if (is_last && tid < NROW) {
        __threadfence();
        float s0 = 0.f, s1 = 0.f, s2 = 0.f, s3 = 0.f;
#pragma unroll
        for (int i = 0; i < NBLK; i += 4) {
            s0 += g_partial[(i + 0) * NROW + tid];
            s1 += g_partial[(i + 1) * NROW + tid];
            s2 += g_partial[(i + 2) * NROW + tid];
            s3 += g_partial[(i + 3) * NROW + tid];
        }
        out[tid] = (s0 + s1) + (s2 + s3);
        if (tid == 0) g_count = 0;         // reset for next graph replay
    }
}

extern "C" void kernel_launch(void* const* d_in, const int* in_sizes, int n_in,
                              void* d_out, int out_size) {
    (void)in_sizes; (void)n_in; (void)out_size;
    const float* x = (const float*)d_in[0];
    const float* w = (const float*)d_in[1];
    // d_in[2] (comb_idx) intentionally unused: lexicographic rank is closed-form.

    honu_prep<<<129, 256>>>(w);

    size_t smem_bytes = (size_t)(130 * NROW + WPB * 128) * sizeof(float);  // 141,312 B
    cudaFuncSetAttribute(honu_main, cudaFuncAttributeMaxDynamicSharedMemorySize,
                         (int)smem_bytes);
    honu_main<<<NBLK, 512, smem_bytes>>>(x, (float*)d_out);
}

// round 10
// speedup vs baseline: 1.7638x; 1.7638x over previous
#include <cuda_runtime.h>

// HONU degree-3: out[r] = sum_{a<=b<=c} w(a,b,c) * xs[a][r]*xs[b][r]*xs[c][r]
// xs[0][r]=1 (bias). Weight index = lexicographic rank (closed form); the
// comb_idx input is redundant and ignored.
//
// Pair factorization: s_ab[r] = sum_c w_abc * xs[c][r];
//                     out[r] += xs[a][r]*xs[b][r]*s_ab[r].
// FOUR 'a'-streams share each xs[c] LDS.128; each warp owns ALL 256 rows
// (8 rows/thread = 4x packed fma.rn.f32x2). 4 streams keeps live state ~85
// regs -> no spills (R6/R7/R9 all spilled with 8 streams). Weights read
// directly (uniform LDG.32, pack2 = 1 MOV), unroll-2 with front-loaded loads;
// 4 warps/SMSP hide L2 latency. Single launch, grid=148 (1 wave), 512 thr.
// Cross-block reduction fused via atomic ticket.

#define NFEAT 129
#define NROW  256
#define NBLK  148
#define WPB   16
#define NRANGE (NBLK * WPB)   // 2368 ranges, one warp each (full 256 rows)

__host__ __device__ __forceinline__ int c2i(int v) { return v * (v - 1) / 2; }
__host__ __device__ __forceinline__ int c3i(int v) { return v * (v - 1) * (v - 2) / 6; }

// flat lexicographic rank of combo (a, b, b); total combos = C(131,3) = 366145
__device__ __forceinline__ int comb_base(int a, int b) {
    return 366145 - c3i(131 - a) + c2i(130 - a) - c2i(130 - b);
}

// total c-steps over all (b, quartet) rows: sum_b (b/4+1)*(129-b)
constexpr int t4_calc() {
    int t = 0;
    for (int b = 0; b < NFEAT; b++) t += (b / 4 + 1) * (NFEAT - b);
    return t;
}
constexpr int T4 = t4_calc();

__device__ float g_partial[NBLK * NROW];
__device__ int   g_count = 0;

__device__ __forceinline__ unsigned long long pack2(float w) {
    unsigned long long r;
    unsigned int wi = __float_as_uint(w);
    asm("mov.b64 %0, {%1, %1};" : "=l"(r) : "r"(wi));
    return r;
}
__device__ __forceinline__ void fma2(unsigned long long& d, unsigned long long a,
                                     unsigned long long b) {
    asm("fma.rn.f32x2 %0, %1, %2, %0;" : "+l"(d) : "l"(a), "l"(b));
}
__device__ __forceinline__ unsigned long long mul2(unsigned long long a,
                                                   unsigned long long b) {
    unsigned long long d;
    asm("mul.rn.f32x2 %0, %1, %2;" : "=l"(d) : "l"(a), "l"(b));
    return d;
}

__global__ void __launch_bounds__(512, 1)
honu_main(const float* __restrict__ x, const float* __restrict__ w,
          float* __restrict__ out) {
    extern __shared__ float smem[];
    float* xs   = smem;                   // [129][256] feature-major
    float* obuf = smem + NFEAT * NROW;    // [16][256] per-warp partials
    __shared__ int sP4[130];              // prefix of c-steps before feature b
    __shared__ int is_last;

    int tid = threadIdx.x;

    // ---- prefix table ----
    if (tid < 130) {
        int p = 0;
        for (int bb = 0; bb < tid && bb < NFEAT; bb++)
            p += (bb / 4 + 1) * (NFEAT - bb);
        sP4[tid] = p;                     // sP4[129] == T4
    }

    // ---- x transposed into smem (both 256-thread halves do 64 features) ----
    {
        int r = tid & 255, h = tid >> 8;
        const float4* xg = (const float4*)(x + (size_t)r * 128 + h * 64);
#pragma unroll
        for (int k = 0; k < 16; k++) {
            float4 v = xg[k];
            int f = h * 64 + 4 * k;
            xs[(f + 1) * NROW + r] = v.x;
            xs[(f + 2) * NROW + r] = v.y;
            xs[(f + 3) * NROW + r] = v.z;
            xs[(f + 4) * NROW + r] = v.w;
        }
        if (h == 0) xs[r] = 1.0f;         // bias feature
    }
    __syncthreads();

    int warp = tid >> 5, lane = tid & 31;
    int range = blockIdx.x * WPB + warp;

    int s = (int)(((long long)T4 * range) / NRANGE);
    int e = (int)(((long long)T4 * (range + 1)) / NRANGE);

    // ---- decode start -> (b, quartet o, c-offset) via binary search ----
    int lo = 0, hi = NFEAT - 1;
    while (lo < hi) {                     // largest b with sP4[b] <= s
        int mid = (lo + hi + 1) >> 1;
        if (sP4[mid] <= s) lo = mid; else hi = mid - 1;
    }
    int b = lo;
    int rem = s - sP4[b];
    int L = NFEAT - b;
    int o = rem / L;
    int coff = rem % L;
    int pos = s;

    unsigned long long ov[4] = {0, 0, 0, 0};      // 8 rows as 4x f32x2

    const ulonglong2* xs2 = (const ulonglong2*)xs;  // 64 16B-quads per feature

    while (pos < e) {
        L = NFEAT - b;
        int a0 = o << 2;
        int na = b + 1 - a0;
        if (na > 4) na = 4;
        int seg = L - coff;
        if (seg > e - pos) seg = e - pos;

        const float* wp[4];
#pragma unroll
        for (int j = 0; j < 4; j++) {
            int aj = (j < na) ? (a0 + j) : a0;   // dead streams alias stream 0
            wp[j] = w + comb_base(aj, b) + coff;
        }

        unsigned long long acc[4][4];
#pragma unroll
        for (int j = 0; j < 4; j++) {
            acc[j][0] = 0; acc[j][1] = 0; acc[j][2] = 0; acc[j][3] = 0;
        }

        const ulonglong2* xp = xs2 + (size_t)(b + coff) * 64 + lane;

        int q = 0;
        for (; q + 2 <= seg; q += 2) {
            float wa[4], wb[4];                  // front-loaded: 8 LDGs in flight
#pragma unroll
            for (int j = 0; j < 4; j++) {
                wa[j] = __ldg(wp[j] + q);
                wb[j] = __ldg(wp[j] + q + 1);
            }
            ulonglong2 x0 = xp[0];               // rows 0-127  (feature b+coff+q)
            ulonglong2 x1 = xp[32];              // rows 128-255
#pragma unroll
            for (int j = 0; j < 4; j++) {
                unsigned long long w2 = pack2(wa[j]);
                fma2(acc[j][0], w2, x0.x);
                fma2(acc[j][1], w2, x0.y);
                fma2(acc[j][2], w2, x1.x);
                fma2(acc[j][3], w2, x1.y);
            }
            ulonglong2 x2 = xp[64];              // feature +1
            ulonglong2 x3 = xp[96];
#pragma unroll
            for (int j = 0; j < 4; j++) {
                unsigned long long w2 = pack2(wb[j]);
                fma2(acc[j][0], w2, x2.x);
                fma2(acc[j][1], w2, x2.y);
                fma2(acc[j][2], w2, x3.x);
                fma2(acc[j][3], w2, x3.y);
            }
            xp += 128;
        }
        if (q < seg) {                            // odd tail step
            ulonglong2 x0 = xp[0];
            ulonglong2 x1 = xp[32];
#pragma unroll
            for (int j = 0; j < 4; j++) {
                unsigned long long w2 = pack2(__ldg(wp[j] + q));
                fma2(acc[j][0], w2, x0.x);
                fma2(acc[j][1], w2, x0.y);
                fma2(acc[j][2], w2, x1.x);
                fma2(acc[j][3], w2, x1.y);
            }
        }

        // epilogue: out += (x_a * x_b) * s_ab  (linearity allows partial runs)
        {
            const ulonglong2* xbp = xs2 + (size_t)b * 64 + lane;
            ulonglong2 xb0 = xbp[0];
            ulonglong2 xb1 = xbp[32];
#pragma unroll
            for (int j = 0; j < 4; j++) {
                if (j < na) {
                    const ulonglong2* xap = xs2 + (size_t)(a0 + j) * 64 + lane;
                    ulonglong2 xa0 = xap[0];
                    ulonglong2 xa1 = xap[32];
                    fma2(ov[0], mul2(xa0.x, xb0.x), acc[j][0]);
                    fma2(ov[1], mul2(xa0.y, xb0.y), acc[j][1]);
                    fma2(ov[2], mul2(xa1.x, xb1.x), acc[j][2]);
                    fma2(ov[3], mul2(xa1.y, xb1.y), acc[j][3]);
                }
            }
        }

        pos += seg;
        coff += seg;
        if (coff == L) {
            coff = 0;
            o++;
            if ((o << 2) > b) { o = 0; b++; }
        }
    }

    // ---- per-warp partials -> smem, block combine -> global partial ----
    {
        float4* ob = (float4*)(obuf + warp * NROW);
        union { unsigned long long q[2]; float4 f; } u;
        u.q[0] = ov[0]; u.q[1] = ov[1];
        ob[lane] = u.f;                   // rows 4*lane .. 4*lane+3
        u.q[0] = ov[2]; u.q[1] = ov[3];
        ob[lane + 32] = u.f;              // rows 128+4*lane ..
    }
    __syncthreads();
    if (tid < NROW) {
        float ssum = 0.0f;
#pragma unroll
        for (int k = 0; k < WPB; k++) ssum += obuf[k * NROW + tid];
        g_partial[blockIdx.x * NROW + tid] = ssum;
    }

    // ---- fused cross-block reduction: last block reduces ----
    __threadfence();
    __syncthreads();
    if (tid == 0) is_last = (atomicAdd(&g_count, 1) == NBLK - 1);
    __syncthreads();
    if (is_last && tid < NROW) {
        __threadfence();
        float s0 = 0.f, s1 = 0.f, s2 = 0.f, s3 = 0.f;
#pragma unroll
        for (int i = 0; i < NBLK; i += 4) {
            s0 += g_partial[(i + 0) * NROW + tid];
            s1 += g_partial[(i + 1) * NROW + tid];
            s2 += g_partial[(i + 2) * NROW + tid];
            s3 += g_partial[(i + 3) * NROW + tid];
        }
        out[tid] = (s0 + s1) + (s2 + s3);
        if (tid == 0) g_count = 0;        // reset for next graph replay
    }
}

extern "C" void kernel_launch(void* const* d_in, const int* in_sizes, int n_in,
                              void* d_out, int out_size) {
    (void)in_sizes; (void)n_in; (void)out_size;
    const float* x = (const float*)d_in[0];
    const float* w = (const float*)d_in[1];
    // d_in[2] (comb_idx) intentionally unused: lexicographic rank is closed-form.

    size_t smem_bytes = (size_t)(NFEAT * NROW + WPB * NROW) * sizeof(float);  // 148,480 B
    cudaFuncSetAttribute(honu_main, cudaFuncAttributeMaxDynamicSharedMemorySize,
                         (int)smem_bytes);
    honu_main<<<NBLK, 512, smem_bytes>>>(x, w, (float*)d_out);
}